// round 1
// baseline (speedup 1.0000x reference)
#include <cuda_runtime.h>

#define THREADS  128
#define NTERMS   48
#define NBUCKETS 64
#define DIM4     128   // 512 floats = 128 float4

__device__ double g_sum[NBUCKETS];
__device__ double g_cnt[NBUCKETS];
__device__ float  g_recip[NTERMS];
__device__ float  g_C;
__device__ int    g_is64;

// Re-initialized on every launch (graph replay safe, deterministic).
__global__ void nll_init() {
    int j = threadIdx.x;
    if (j < NBUCKETS) { g_sum[j] = 0.0; g_cnt[j] = 0.0; }
    if (j >= 1 && j < NTERMS)
        g_recip[j] = 1.0f / ((float)j * (255.0f + (float)j));
    if (j == 0) {
        // C = 255*ln2 + lgamma(256) - 256*ln(2*pi)
        g_C = (float)(255.0 * 0.6931471805599453
                      + lgamma(256.0)
                      - 256.0 * 1.8378770664093453);
        g_is64 = 1;
    }
}

// Detect whether target buffer is int64 or (jax-demoted) int32.
// Reads only the first n/2 int64 words = first n*4 bytes, in-bounds for both layouts.
__global__ void nll_detect(const long long* __restrict__ t64, int n_half, long long vocab) {
    int i = blockIdx.x * blockDim.x + threadIdx.x;
    if (i < n_half) {
        long long v = t64[i];
        if (v < 0 || v >= vocab) g_is64 = 0;   // race-free: all writers store 0
    }
}

__global__ void __launch_bounds__(THREADS)
nll_main(const float* __restrict__ preds,
         const void*  __restrict__ target,
         const float* __restrict__ emb,
         int n)
{
    int row = blockIdx.x;
    if (row >= n) return;

    long long t;
    if (g_is64) t = ((const long long*)target)[row];
    else        t = (long long)((const int*)target)[row];

    int tid = threadIdx.x;
    const float4* p = reinterpret_cast<const float4*>(preds) + (size_t)row * DIM4 + tid;
    const float4* e = reinterpret_cast<const float4*>(emb)   + (size_t)t   * DIM4 + tid;
    float4 pv = *p;
    float4 ev = *e;

    float ss = pv.x*pv.x + pv.y*pv.y + pv.z*pv.z + pv.w*pv.w;  // ||preds||^2 partial
    float dt = pv.x*ev.x + pv.y*ev.y + pv.z*ev.z + pv.w*ev.w;  // dot partial

    #pragma unroll
    for (int o = 16; o > 0; o >>= 1) {
        ss += __shfl_down_sync(0xffffffffu, ss, o);
        dt += __shfl_down_sync(0xffffffffu, dt, o);
    }

    __shared__ float s_ss[4], s_dt[4];
    if ((tid & 31) == 0) { s_ss[tid >> 5] = ss; s_dt[tid >> 5] = dt; }
    __syncthreads();

    if (tid == 0 && t != 1) {   // PAD_ID == 1
        float sumsq = s_ss[0] + s_ss[1] + s_ss[2] + s_ss[3];
        float dot   = s_dt[0] + s_dt[1] + s_dt[2] + s_dt[3];
        float z = sqrtf(sumsq);
        float x = 0.25f * sumsq;

        // S = sum_j x^j / (j! * (256)_j); t0 = 1 dominates, converges < 20 terms.
        float S = 1.0f, term = 1.0f;
        #pragma unroll
        for (int j = 1; j < NTERMS; j++) {
            term *= x * g_recip[j];
            S += term;
        }

        // loss = logS - z - dot - C
        float loss = logf(S) - z - dot - g_C;

        int b = row & (NBUCKETS - 1);
        atomicAdd(&g_sum[b], (double)loss);
        atomicAdd(&g_cnt[b], 1.0);
    }
}

__global__ void nll_fin(float* out, int m) {
    double s = 0.0, c = 0.0;
    #pragma unroll
    for (int i = 0; i < NBUCKETS; i++) { s += g_sum[i]; c += g_cnt[i]; }
    float r = (float)(s / c);
    for (int i = 0; i < m; i++) out[i] = r;
}

extern "C" void kernel_launch(void* const* d_in, const int* in_sizes, int n_in,
                              void* d_out, int out_size) {
    const float* preds  = (const float*)d_in[0];
    const void*  target = d_in[1];
    const float* emb    = (const float*)d_in[2];
    int n = in_sizes[1];                              // B*S rows
    long long vocab = (long long)(in_sizes[2] / 512); // rows of emb table

    nll_init<<<1, 64>>>();
    int nd = n / 2;
    nll_detect<<<(nd + 255) / 256, 256>>>((const long long*)target, nd, vocab);
    nll_main<<<n, THREADS>>>(preds, target, emb, n);
    nll_fin<<<1, 1>>>((float*)d_out, out_size);
}

// round 2
// speedup vs baseline: 1.2149x; 1.2149x over previous
#include <cuda_runtime.h>

#define THREADS  128
#define NTERMS   48
#define NBUCKETS 64
#define DIM4     128   // 512 floats = 128 float4

// All zero at module load; the finalizing block restores them to zero every
// launch, so graph replays are deterministic with no init kernel.
__device__ double   g_sum[NBUCKETS];
__device__ double   g_cnt[NBUCKETS];
__device__ unsigned g_ticket;
__device__ int      g_flag32;   // 1 => target buffer is int32 (jax demoted)

// C = 255*ln2 + lgamma(256) - 256*ln(2*pi), precomputed in double:
// 255*0.693147180559945 = 176.752531042786
// lgamma(256)           = 1161.71210111840
// 256*1.837877066409345 = 470.496529000792
#define LOSS_C 867.968103160394f

// Detect whether target buffer is int64 or int32. Reads first n/2 int64 words
// = first n*4 bytes, in-bounds for both layouts. int32 layout makes the high
// word of most int64 reads a nonzero target value => out-of-range => flag.
__global__ void nll_detect(const long long* __restrict__ t64, int n_half, long long vocab) {
    int i = blockIdx.x * blockDim.x + threadIdx.x;
    if (i < n_half) {
        long long v = t64[i];
        if (v < 0 || v >= vocab) g_flag32 = 1;   // all writers store 1: race-free
    }
}

__global__ void __launch_bounds__(THREADS)
nll_main(const float* __restrict__ preds,
         const void*  __restrict__ target,
         const float* __restrict__ emb,
         float* __restrict__ out, int out_size)
{
    int row = blockIdx.x;
    int tid = threadIdx.x;

    long long t;
    if (g_flag32) t = (long long)((const int*)target)[row];
    else          t = ((const long long*)target)[row];

    const float4* p = reinterpret_cast<const float4*>(preds) + (size_t)row * DIM4 + tid;
    const float4* e = reinterpret_cast<const float4*>(emb)   + (size_t)t   * DIM4 + tid;
    float4 pv = *p;
    float4 ev = *e;

    float ss = pv.x*pv.x + pv.y*pv.y + pv.z*pv.z + pv.w*pv.w;  // ||preds||^2 partial
    float dt = pv.x*ev.x + pv.y*ev.y + pv.z*ev.z + pv.w*ev.w;  // dot partial

    #pragma unroll
    for (int o = 16; o > 0; o >>= 1) {
        ss += __shfl_down_sync(0xffffffffu, ss, o);
        dt += __shfl_down_sync(0xffffffffu, dt, o);
    }

    __shared__ float s_ss[4], s_dt[4];
    if ((tid & 31) == 0) { s_ss[tid >> 5] = ss; s_dt[tid >> 5] = dt; }
    __syncthreads();

    if (tid == 0 && t != 1) {   // PAD_ID == 1
        float sumsq = s_ss[0] + s_ss[1] + s_ss[2] + s_ss[3];
        float dot   = s_dt[0] + s_dt[1] + s_dt[2] + s_dt[3];
        float z = sqrtf(sumsq);
        float x = 0.25f * sumsq;

        // S = sum_j x^j / (j! * (256)_j); t0 = 1 dominates, converges < 20 terms.
        // Reciprocals are compile-time constants after unroll.
        float S = 1.0f, term = 1.0f;
        #pragma unroll
        for (int j = 1; j < NTERMS; j++) {
            term *= x * (1.0f / ((float)j * (255.0f + (float)j)));
            S += term;
        }

        float loss = logf(S) - z - dot - LOSS_C;

        int b = row & (NBUCKETS - 1);
        atomicAdd(&g_sum[b], (double)loss);
        atomicAdd(&g_cnt[b], 1.0);
    }

    // ---- last-block finalize + state reset (replaces the fin kernel) ----
    __shared__ unsigned s_tkt;
    if (tid == 0) {
        __threadfence();                       // make this block's atomics visible
        s_tkt = atomicAdd(&g_ticket, 1u);
    }
    __syncthreads();

    if (s_tkt == gridDim.x - 1) {
        __threadfence();                       // see all other blocks' atomics
        double s = 0.0, c = 0.0;
        if (tid < NBUCKETS) { s = g_sum[tid]; c = g_cnt[tid]; }
        #pragma unroll
        for (int o = 16; o > 0; o >>= 1) {
            s += __shfl_down_sync(0xffffffffu, s, o);
            c += __shfl_down_sync(0xffffffffu, c, o);
        }
        __shared__ double sh_s[2], sh_c[2];
        if (tid < NBUCKETS && (tid & 31) == 0) { sh_s[tid >> 5] = s; sh_c[tid >> 5] = c; }
        __syncthreads();
        if (tid == 0) {
            float r = (float)((sh_s[0] + sh_s[1]) / (sh_c[0] + sh_c[1]));
            for (int i = 0; i < out_size; i++) out[i] = r;
            g_ticket = 0u;
            g_flag32 = 0;
        }
        if (tid < NBUCKETS) { g_sum[tid] = 0.0; g_cnt[tid] = 0.0; }
    }
}

extern "C" void kernel_launch(void* const* d_in, const int* in_sizes, int n_in,
                              void* d_out, int out_size) {
    const float* preds  = (const float*)d_in[0];
    const void*  target = d_in[1];
    const float* emb    = (const float*)d_in[2];
    int n = in_sizes[1];                              // B*S rows
    long long vocab = (long long)(in_sizes[2] / 512); // rows of emb table

    int nd = n / 2;
    nll_detect<<<(nd + 255) / 256, 256>>>((const long long*)target, nd, vocab);
    nll_main<<<n, THREADS>>>(preds, target, emb, (float*)d_out, out_size);
}

// round 3
// speedup vs baseline: 1.5212x; 1.2521x over previous
#include <cuda_runtime.h>

#define THREADS  256
#define WPB      (THREADS / 32)     // 8 warps per block
#define RPW      2                  // rows per warp
#define RPB      (WPB * RPW)        // 16 rows per block
#define NTERMS   48
#define NBUCKETS 64
#define DIM4     128                // 512 floats = 128 float4

// All zero at module load; the finalizing block restores them to zero every
// launch, so graph replays are deterministic with no init kernel.
__device__ double   g_sum[NBUCKETS];
__device__ double   g_cnt[NBUCKETS];
__device__ unsigned g_ticket;
__device__ int      g_flag32;   // 1 => target buffer is int32 (jax demoted)

// C = 255*ln2 + lgamma(256) - 256*ln(2*pi)
#define LOSS_C 867.968103160394f

__device__ __forceinline__ float dot4(float4 a, float4 b) {
    return a.x*b.x + a.y*b.y + a.z*b.z + a.w*b.w;
}

// Detect whether target buffer is int64 or int32. Reads first n/2 int64 words
// = first n*4 bytes, in-bounds for both layouts.
__global__ void nll_detect(const long long* __restrict__ t64, int n_half, long long vocab) {
    int i = blockIdx.x * blockDim.x + threadIdx.x;
    if (i < n_half) {
        long long v = t64[i];
        if (v < 0 || v >= vocab) g_flag32 = 1;   // all writers store 1: race-free
    }
}

__global__ void __launch_bounds__(THREADS)
nll_main(const float* __restrict__ preds,
         const void*  __restrict__ target,
         const float* __restrict__ emb,
         float* __restrict__ out, int out_size, int n)
{
    int tid  = threadIdx.x;
    int lane = tid & 31;
    int w    = tid >> 5;
    int row0 = blockIdx.x * RPB + w * RPW;
    int flag = g_flag32;

    // Batch-load this warp's targets (lanes 0..RPW-1), broadcast via shuffle.
    long long t_l = 1;   // PAD default (skipped, but still a valid emb row)
    if (lane < RPW) {
        int r = row0 + lane;
        if (r < n) {
            t_l = flag ? (long long)((const int*)target)[r]
                       : ((const long long*)target)[r];
        }
    }

    float wsum = 0.0f;   // lane-0 accumulators across this warp's rows
    int   wcnt = 0;

    #pragma unroll
    for (int rr = 0; rr < RPW; rr++) {
        int row = row0 + rr;
        if (row >= n) break;   // uniform within warp
        long long t = __shfl_sync(0xffffffffu, t_l, rr);

        const float4* p = reinterpret_cast<const float4*>(preds) + (size_t)row * DIM4 + lane;
        const float4* e = reinterpret_cast<const float4*>(emb)   + (size_t)t   * DIM4 + lane;

        float4 a0 = p[0], a1 = p[32], a2 = p[64], a3 = p[96];
        float4 b0 = e[0], b1 = e[32], b2 = e[64], b3 = e[96];

        float ss = dot4(a0,a0) + dot4(a1,a1) + dot4(a2,a2) + dot4(a3,a3);
        float dt = dot4(a0,b0) + dot4(a1,b1) + dot4(a2,b2) + dot4(a3,b3);

        #pragma unroll
        for (int o = 16; o > 0; o >>= 1) {
            ss += __shfl_down_sync(0xffffffffu, ss, o);
            dt += __shfl_down_sync(0xffffffffu, dt, o);
        }

        if (lane == 0 && t != 1) {   // PAD_ID == 1
            float z = sqrtf(ss);
            float x = 0.25f * ss;
            // S = sum_j x^j / (j! * (256)_j); constants fold at compile time.
            float S = 1.0f, term = 1.0f;
            #pragma unroll
            for (int j = 1; j < NTERMS; j++) {
                term *= x * (1.0f / ((float)j * (255.0f + (float)j)));
                S += term;
            }
            wsum += logf(S) - z - dt - LOSS_C;
            wcnt += 1;
        }
    }

    if (lane == 0 && wcnt > 0) {
        int b = (blockIdx.x * WPB + w) & (NBUCKETS - 1);
        atomicAdd(&g_sum[b], (double)wsum);
        atomicAdd(&g_cnt[b], (double)wcnt);
        __threadfence();   // release this warp's contributions
    }

    // ---- last-block finalize + state reset ----
    __syncthreads();
    __shared__ unsigned s_tkt;
    if (tid == 0) s_tkt = atomicAdd(&g_ticket, 1u);
    __syncthreads();

    if (s_tkt == gridDim.x - 1) {
        __threadfence();   // acquire: see all blocks' atomics
        double s = 0.0, c = 0.0;
        if (tid < NBUCKETS) { s = g_sum[tid]; c = g_cnt[tid]; }
        #pragma unroll
        for (int o = 16; o > 0; o >>= 1) {
            s += __shfl_down_sync(0xffffffffu, s, o);
            c += __shfl_down_sync(0xffffffffu, c, o);
        }
        __shared__ double sh_s[2], sh_c[2];
        if (tid < NBUCKETS && lane == 0) { sh_s[tid >> 5] = s; sh_c[tid >> 5] = c; }
        __syncthreads();
        if (tid == 0) {
            float r = (float)((sh_s[0] + sh_s[1]) / (sh_c[0] + sh_c[1]));
            for (int i = 0; i < out_size; i++) out[i] = r;
            g_ticket = 0u;
            g_flag32 = 0;
        }
        if (tid < NBUCKETS) { g_sum[tid] = 0.0; g_cnt[tid] = 0.0; }
    }
}

extern "C" void kernel_launch(void* const* d_in, const int* in_sizes, int n_in,
                              void* d_out, int out_size) {
    const float* preds  = (const float*)d_in[0];
    const void*  target = d_in[1];
    const float* emb    = (const float*)d_in[2];
    int n = in_sizes[1];                              // B*S rows
    long long vocab = (long long)(in_sizes[2] / 512); // rows of emb table

    int nd = n / 2;
    nll_detect<<<(nd + 255) / 256, 256>>>((const long long*)target, nd, vocab);
    int blocks = (n + RPB - 1) / RPB;
    nll_main<<<blocks, THREADS>>>(preds, target, emb, (float*)d_out, out_size, n);
}